// round 12
// baseline (speedup 1.0000x reference)
#include <cuda_runtime.h>
#include <math.h>

// Problem constants (fixed by setup_inputs)
#define BB    8
#define NT    14
#define NF    72
#define NTOK  1008          // NT*NF
#define DM    256
#define NH    8
#define DK    32
#define NFREQ 8             // d_rpe/2/2
#define NDT   27            // 2*NT-1
#define NDF   143           // 2*NF-1
#define TBL   (NDT*NDF)     // 3861
#define MTOT  (BB*NTOK)     // 8064
#define BH    (BB*NH)       // 64
#define BROW  1024          // padded k-stride of g_B

// Dynamic smem layout for attn_kernel (32-bit word offsets)
#define W_PQ    0           // 64*68 = 4352 words (Q staging stride 36, then P stride 68)
#define W_RING  4352        // 2 slots x (K 64*36=2304 + V 64*40=2560) = 2*4864
#define W_REDS  14080       // 128 floats
#define DYN_WORDS 14208
#define DYN_BYTES (DYN_WORDS * 4)   // 56832

// Scratch (device globals; module-static, no runtime allocation)
__device__ float g_table[NH * TBL];
__device__ float g_B[NH * NTOK * BROW];     // precomputed bias matrix, 33 MB
__device__ float g_Q[BH * NTOK * DK];
__device__ float g_K[BH * NTOK * DK];
__device__ float g_V[BH * NTOK * DK];
__device__ float g_AO[MTOT * DM];

// Resolved input pointers (filled by classify_kernel on device)
__device__ const float* dp_qt;
__device__ const float* dp_kt;
__device__ const float* dp_vt;
__device__ const int*   dp_tq;
__device__ const int*   dp_fq;
__device__ const int*   dp_tk;
__device__ const int*   dp_fk;
__device__ const float* dp_Wq;
__device__ const float* dp_Wk;
__device__ const float* dp_Wv;
__device__ const float* dp_Wo;
__device__ const float* dp_Wrpe;

// ---------------------------------------------------------------------------
// tf32 helpers
// ---------------------------------------------------------------------------
__device__ __forceinline__ unsigned tf32u(float f) {
    unsigned u;
    asm("cvt.rna.tf32.f32 %0, %1;" : "=r"(u) : "f"(f));
    return u;
}

__device__ __forceinline__ void mma_tf32(float4& d, unsigned a0, unsigned a1,
                                         unsigned a2, unsigned a3,
                                         unsigned b0, unsigned b1) {
    asm("mma.sync.aligned.m16n8k8.row.col.f32.tf32.tf32.f32 "
        "{%0,%1,%2,%3},{%4,%5,%6,%7},{%8,%9},{%0,%1,%2,%3};"
        : "+f"(d.x), "+f"(d.y), "+f"(d.z), "+f"(d.w)
        : "r"(a0), "r"(a1), "r"(a2), "r"(a3), "r"(b0), "r"(b1));
}

// ---------------------------------------------------------------------------
// 0) Classify inputs by content (ordering-agnostic).
// ---------------------------------------------------------------------------
__global__ void classify_kernel(const float* t0, const float* t1, const float* t2,
                                const int* p0, const int* p1, const int* p2, const int* p3,
                                const float* w0, const float* w1, const float* w2, const float* w3,
                                const float* wr) {
    __shared__ int mres[4];
    int tid = threadIdx.x;
    int w = tid >> 5, lane = tid & 31;
    const int* arr = (w == 0) ? p0 : (w == 1) ? p1 : (w == 2) ? p2 : p3;
    int m = 0;
    for (int i = lane; i < NTOK; i += 32) m = max(m, arr[i]);
#pragma unroll
    for (int off = 16; off > 0; off >>= 1)
        m = max(m, __shfl_xor_sync(0xffffffffu, m, off));
    if (lane == 0) mres[w] = m;
    __syncthreads();
    if (tid == 0) {
        bool T0 = (mres[0] <= NT - 1), T1 = (mres[1] <= NT - 1);
        bool T2 = (mres[2] <= NT - 1), T3 = (mres[3] <= NT - 1);
        if (!T0 && !T1 && T2 && T3) {
            dp_fk = p0; dp_fq = p1; dp_tk = p2; dp_tq = p3;
            dp_kt = t0; dp_qt = t1; dp_vt = t2;
            dp_Wk = w0; dp_Wo = w1; dp_Wq = w2; dp_Wv = w3;
        } else if (T0 && T1 && !T2 && !T3) {
            dp_tq = p0; dp_tk = p1; dp_fq = p2; dp_fk = p3;
            dp_qt = t0; dp_kt = t1; dp_vt = t2;
            dp_Wq = w0; dp_Wk = w1; dp_Wv = w2; dp_Wo = w3;
        } else {
            dp_tq = p0; dp_fq = p1; dp_tk = p2; dp_fk = p3;
            dp_qt = t0; dp_kt = t1; dp_vt = t2;
            dp_Wq = w0; dp_Wk = w1; dp_Wv = w2; dp_Wo = w3;
        }
        dp_Wrpe = wr;
    }
}

// ---------------------------------------------------------------------------
// 1) RPE bias table
// ---------------------------------------------------------------------------
__global__ void bias_table_kernel() {
    int gid = blockIdx.x * blockDim.x + threadIdx.x;
    if (gid >= NH * TBL) return;
    int pos = gid >> 3;
    int h   = gid & 7;
    int dt  = pos / NDF;
    int df  = pos % NDF;
    float pt = (float)(dt - (NT - 1)) / (float)(NT - 1);
    float pf = (float)(df - (NF - 1)) / (float)(NF - 1);
    const float* w = dp_Wrpe + h * 32;
    float acc = 0.f;
    float lg = logf(10000.0f);
#pragma unroll
    for (int j = 0; j < NFREQ; j++) {
        float fr = expf(-lg * (float)j / (float)NFREQ);
        float at = pt * fr;
        float af = pf * fr;
        acc += sinf(at) * w[j];
        acc += cosf(at) * w[NFREQ + j];
        acc += sinf(af) * w[2 * NFREQ + j];
        acc += cosf(af) * w[3 * NFREQ + j];
    }
    g_table[h * TBL + pos] = acc;
}

// ---------------------------------------------------------------------------
// 1b) Bias matrix: g_B[h][q][k] = table[h][...], done ONCE (shared by batches)
// ---------------------------------------------------------------------------
__global__ void bias_mat_kernel() {
    int q = blockIdx.x;
    int h = blockIdx.y;
    int base = (dp_tq[q] + NT - 1) * NDF + dp_fq[q] + NF - 1;
    const float* tb = g_table + h * TBL;
    float* dst = g_B + ((size_t)h * NTOK + q) * BROW;
    for (int k = threadIdx.x; k < NTOK; k += 256)
        dst[k] = tb[base - (dp_tk[k] * NDF + dp_fk[k])];
}

// ---------------------------------------------------------------------------
// 2) GEMM: 128x64 tiles, 8x4 micro, fp32 SIMT.
//    sel 9: fused QKV mode — blockIdx.z selects input 1/2/3.
//    sel 0: output projection, row-major write to outp.
// ---------------------------------------------------------------------------
__global__ void __launch_bounds__(256) gemm_big(float* __restrict__ outp, int sel) {
    if (sel == 9) sel = 1 + blockIdx.z;
    const float* X;
    const float* W;
    if      (sel == 1) { X = dp_qt; W = dp_Wq; }
    else if (sel == 2) { X = dp_kt; W = dp_Wk; }
    else if (sel == 3) { X = dp_vt; W = dp_Wv; }
    else               { X = g_AO;  W = dp_Wo; }

    __shared__ float As[16 * 132];
    __shared__ float Bs[16 * 68];
    int tid = threadIdx.x;
    int ca = tid & 15;
    int ra = tid >> 4;
    int m0 = blockIdx.y << 7;
    int n0 = blockIdx.x << 6;

    float acc[8][4];
#pragma unroll
    for (int i = 0; i < 8; i++)
#pragma unroll
        for (int j = 0; j < 4; j++) acc[i][j] = 0.f;

    for (int k0 = 0; k0 < DM; k0 += 16) {
        __syncthreads();
#pragma unroll
        for (int j = 0; j < 2; j++) {
            int f = tid + j * 256;
            int m = f >> 2, k4 = f & 3;
            float4 v = *(const float4*)(X + (size_t)(m0 + m) * DM + k0 + (k4 << 2));
            As[(k4 * 4 + 0) * 132 + m] = v.x;
            As[(k4 * 4 + 1) * 132 + m] = v.y;
            As[(k4 * 4 + 2) * 132 + m] = v.z;
            As[(k4 * 4 + 3) * 132 + m] = v.w;
        }
        {
            int n = tid >> 2, k4 = tid & 3;
            float4 v = *(const float4*)(W + (size_t)(n0 + n) * DM + k0 + (k4 << 2));
            Bs[(k4 * 4 + 0) * 68 + n] = v.x;
            Bs[(k4 * 4 + 1) * 68 + n] = v.y;
            Bs[(k4 * 4 + 2) * 68 + n] = v.z;
            Bs[(k4 * 4 + 3) * 68 + n] = v.w;
        }
        __syncthreads();
#pragma unroll
        for (int k = 0; k < 16; k++) {
            float4 a0 = *(const float4*)&As[k * 132 + (ra << 2)];
            float4 a1 = *(const float4*)&As[k * 132 + 64 + (ra << 2)];
            float4 b  = *(const float4*)&Bs[k * 68 + (ca << 2)];
            acc[0][0] += a0.x * b.x; acc[0][1] += a0.x * b.y; acc[0][2] += a0.x * b.z; acc[0][3] += a0.x * b.w;
            acc[1][0] += a0.y * b.x; acc[1][1] += a0.y * b.y; acc[1][2] += a0.y * b.z; acc[1][3] += a0.y * b.w;
            acc[2][0] += a0.z * b.x; acc[2][1] += a0.z * b.y; acc[2][2] += a0.z * b.z; acc[2][3] += a0.z * b.w;
            acc[3][0] += a0.w * b.x; acc[3][1] += a0.w * b.y; acc[3][2] += a0.w * b.z; acc[3][3] += a0.w * b.w;
            acc[4][0] += a1.x * b.x; acc[4][1] += a1.x * b.y; acc[4][2] += a1.x * b.z; acc[4][3] += a1.x * b.w;
            acc[5][0] += a1.y * b.x; acc[5][1] += a1.y * b.y; acc[5][2] += a1.y * b.z; acc[5][3] += a1.y * b.w;
            acc[6][0] += a1.z * b.x; acc[6][1] += a1.z * b.y; acc[6][2] += a1.z * b.z; acc[6][3] += a1.z * b.w;
            acc[7][0] += a1.w * b.x; acc[7][1] += a1.w * b.y; acc[7][2] += a1.w * b.z; acc[7][3] += a1.w * b.w;
        }
    }

    int ncol = n0 + (ca << 2);
    if (sel == 0) {
#pragma unroll
        for (int i = 0; i < 8; i++) {
            int m = m0 + ((i < 4) ? (ra * 4 + i) : (64 + ra * 4 + i - 4));
            float4 o = make_float4(acc[i][0], acc[i][1], acc[i][2], acc[i][3]);
            *(float4*)(outp + (size_t)m * DM + ncol) = o;
        }
    } else {
        float* dst = (sel == 1) ? g_Q : (sel == 2) ? g_K : g_V;
        int h = ncol >> 5;
        int d = ncol & 31;
#pragma unroll
        for (int i = 0; i < 8; i++) {
            int m = m0 + ((i < 4) ? (ra * 4 + i) : (64 + ra * 4 + i - 4));
            int b = m / NTOK;
            int nn = m - b * NTOK;
            float4 o = make_float4(acc[i][0], acc[i][1], acc[i][2], acc[i][3]);
            *(float4*)(dst + (size_t)((b * NH + h) * NTOK + nn) * DK + d) = o;
        }
    }
}

// ---------------------------------------------------------------------------
// 3) Flash attention: tf32 mma, max-free softmax, double-buffered KV,
//    ONE full barrier + ONE 64-thread pair barrier per chunk.
// ---------------------------------------------------------------------------
__global__ void __launch_bounds__(256) attn_kernel() {
    extern __shared__ __align__(16) unsigned dyn[];
    unsigned* sPQ   = dyn + W_PQ;             // Q staging then P exchange
    float*    sRedS = (float*)(dyn + W_REDS); // [2][64]

    int tid = threadIdx.x;
    int lane = tid & 31;
    int w = tid >> 5;
    int wm = w >> 1;           // 0..3 -> q rows wm*16..+15
    int wn = w & 1;            // 0..1 -> key/dim half
    int r4 = lane >> 2;        // 0..7
    int cl = lane & 3;         // 0..3
    int q0 = blockIdx.x << 6;
    int h = blockIdx.y, b = blockIdx.z;
    int bh = b * NH + h;

    const float4* Q4 = (const float4*)(g_Q + (size_t)bh * NTOK * DK);
    const float4* K4 = (const float4*)(g_K + (size_t)bh * NTOK * DK);
    const float4* V4 = (const float4*)(g_V + (size_t)bh * NTOK * DK);

    // --- stage Q (scaled, tf32) into sPQ with stride 36 ---
    const float invs = 0.17677669529663688f;   // 1/sqrt(32)
#pragma unroll
    for (int j = 0; j < 2; j++) {
        int f = tid + j * 256;
        int r = f >> 3, c4 = f & 7;
        int qr = q0 + r;
        float4 v = make_float4(0.f, 0.f, 0.f, 0.f);
        if (qr < NTOK) v = Q4[qr * 8 + c4];
        unsigned* dst = &sPQ[r * 36 + (c4 << 2)];
        dst[0] = tf32u(v.x * invs);
        dst[1] = tf32u(v.y * invs);
        dst[2] = tf32u(v.z * invs);
        dst[3] = tf32u(v.w * invs);
    }
    __syncthreads();

    // --- extract Q fragments (held for all chunks) ---
    unsigned qf[4][4];
#pragma unroll
    for (int ks = 0; ks < 4; ks++) {
        int dc = ks * 8 + cl;
        qf[ks][0] = sPQ[(wm * 16 + r4) * 36 + dc];
        qf[ks][1] = sPQ[(wm * 16 + r4 + 8) * 36 + dc];
        qf[ks][2] = sPQ[(wm * 16 + r4) * 36 + dc + 4];
        qf[ks][3] = sPQ[(wm * 16 + r4 + 8) * 36 + dc + 4];
    }
    int row0 = wm * 16 + r4;
    int row1 = row0 + 8;
    const float* Bq0 = g_B + ((size_t)h * NTOK + min(q0 + row0, NTOK - 1)) * BROW;
    const float* Bq1 = g_B + ((size_t)h * NTOK + min(q0 + row1, NTOK - 1)) * BROW;

    float l0r = 0.f, l1r = 0.f;
    float4 o0 = make_float4(0.f, 0.f, 0.f, 0.f);
    float4 o1 = make_float4(0.f, 0.f, 0.f, 0.f);

    // per-thread staging slots for prefetch
    int pr = tid >> 3;             // row 0..31 (j=0) / +32 (j=1)
    int pc4 = tid & 7;             // col group
    float4 kvp[2], vvp[2];

    // --- prologue: load chunk 0 into registers ---
#pragma unroll
    for (int j = 0; j < 2; j++) {
        int r = pr + j * 32;
        kvp[j] = K4[r * 8 + pc4];
        vvp[j] = V4[r * 8 + pc4];
    }

    for (int kc = 0; kc < 16; kc++) {
        int k0 = kc << 6;
        unsigned* sKb = dyn + W_RING + (kc & 1) * 4864;
        unsigned* sVb = sKb + 2304;

        // --- store chunk kc from regs to its slot (disjoint from slot kc-1
        //     still being read by slower threads) ---
#pragma unroll
        for (int j = 0; j < 2; j++) {
            int r = pr + j * 32;
            unsigned* dk = &sKb[r * 36 + (pc4 << 2)];
            dk[0] = tf32u(kvp[j].x); dk[1] = tf32u(kvp[j].y);
            dk[2] = tf32u(kvp[j].z); dk[3] = tf32u(kvp[j].w);
            unsigned* dv = &sVb[r * 40 + (pc4 << 2)];
            dv[0] = tf32u(vvp[j].x); dv[1] = tf32u(vvp[j].y);
            dv[2] = tf32u(vvp[j].z); dv[3] = tf32u(vvp[j].w);
        }
        __syncthreads();   // the ONLY full barrier per chunk

        // --- issue bias loads for THIS chunk (coalesced, L2-resident) ---
        float2 b0v[4], b1v[4];
#pragma unroll
        for (int nt = 0; nt < 4; nt++) {
            int col = k0 + wn * 32 + nt * 8 + 2 * cl;   // < 1024 (padded row)
            b0v[nt] = *(const float2*)(Bq0 + col);
            b1v[nt] = *(const float2*)(Bq1 + col);
        }

        // --- issue prefetch for next chunk (hidden behind mma work) ---
        if (kc < 15) {
            int nk0 = k0 + 64;
#pragma unroll
            for (int j = 0; j < 2; j++) {
                int kr = nk0 + pr + j * 32;
                if (kr < NTOK) {
                    kvp[j] = K4[kr * 8 + pc4];
                    vvp[j] = V4[kr * 8 + pc4];
                } else {
                    kvp[j] = make_float4(0.f, 0.f, 0.f, 0.f);
                    vvp[j] = make_float4(0.f, 0.f, 0.f, 0.f);
                }
            }
        }

        // --- scores: S = Q K^T (per warp: 16q x 32k) ---
        float4 c[4];
#pragma unroll
        for (int nt = 0; nt < 4; nt++) c[nt] = make_float4(0.f, 0.f, 0.f, 0.f);
#pragma unroll
        for (int nt = 0; nt < 4; nt++) {
            int key = wn * 32 + nt * 8 + r4;
#pragma unroll
            for (int ks = 0; ks < 4; ks++) {
                int dd = ks * 8 + cl;
                unsigned b0 = sKb[key * 36 + dd];
                unsigned b1 = sKb[key * 36 + dd + 4];
                mma_tf32(c[nt], qf[ks][0], qf[ks][1], qf[ks][2], qf[ks][3], b0, b1);
            }
        }

        // --- bias + exp (max-free) + partial sums + write P ---
        int rem = NTOK - k0;
#pragma unroll
        for (int nt = 0; nt < 4; nt++) {
            int col0 = wn * 32 + nt * 8 + 2 * cl;
            bool v0 = col0 < rem, v1 = col0 + 1 < rem;
            c[nt].x = v0 ? __expf(c[nt].x + b0v[nt].x) : 0.f;
            c[nt].y = v1 ? __expf(c[nt].y + b0v[nt].y) : 0.f;
            c[nt].z = v0 ? __expf(c[nt].z + b1v[nt].x) : 0.f;
            c[nt].w = v1 ? __expf(c[nt].w + b1v[nt].y) : 0.f;
            l0r += c[nt].x + c[nt].y;
            l1r += c[nt].z + c[nt].w;
            uint2 pa; pa.x = tf32u(c[nt].x); pa.y = tf32u(c[nt].y);
            uint2 pb; pb.x = tf32u(c[nt].z); pb.y = tf32u(c[nt].w);
            *(uint2*)&sPQ[row0 * 68 + col0] = pa;
            *(uint2*)&sPQ[row1 * 68 + col0] = pb;
        }
        // pair barrier: only the two warps sharing q-rows wm*16..+15 exchange P
        asm volatile("bar.sync %0, %1;" :: "r"(wm + 1), "r"(64) : "memory");

        // --- PV: O += P V (per warp: 16q x 16d) ---
#pragma unroll
        for (int ks = 0; ks < 8; ks++) {
            int kcidx = ks * 8 + cl;
            unsigned a0 = sPQ[row0 * 68 + kcidx];
            unsigned a1 = sPQ[row1 * 68 + kcidx];
            unsigned a2 = sPQ[row0 * 68 + kcidx + 4];
            unsigned a3 = sPQ[row1 * 68 + kcidx + 4];
            {
                int dcol = wn * 16 + r4;
                unsigned b0 = sVb[kcidx * 40 + dcol];
                unsigned b1 = sVb[(kcidx + 4) * 40 + dcol];
                mma_tf32(o0, a0, a1, a2, a3, b0, b1);
            }
            {
                int dcol = wn * 16 + 8 + r4;
                unsigned b0 = sVb[kcidx * 40 + dcol];
                unsigned b1 = sVb[(kcidx + 4) * 40 + dcol];
                mma_tf32(o1, a0, a1, a2, a3, b0, b1);
            }
        }
    }

    // --- epilogue: one-time row-sum reduction, then normalize & store ---
    l0r += __shfl_xor_sync(0xffffffffu, l0r, 1);
    l0r += __shfl_xor_sync(0xffffffffu, l0r, 2);
    l1r += __shfl_xor_sync(0xffffffffu, l1r, 1);
    l1r += __shfl_xor_sync(0xffffffffu, l1r, 2);
    if (cl == 0) {
        sRedS[wn * 64 + row0] = l0r;
        sRedS[wn * 64 + row1] = l1r;
    }
    __syncthreads();
    float inv0 = 1.0f / (sRedS[row0] + sRedS[64 + row0]);
    float inv1 = 1.0f / (sRedS[row1] + sRedS[64 + row1]);

    int qr0 = q0 + row0, qr1 = q0 + row1;
    int dbase = h * DK + wn * 16 + 2 * cl;
    if (qr0 < NTOK) {
        *(float2*)&g_AO[(size_t)(b * NTOK + qr0) * DM + dbase] =
            make_float2(o0.x * inv0, o0.y * inv0);
        *(float2*)&g_AO[(size_t)(b * NTOK + qr0) * DM + dbase + 8] =
            make_float2(o1.x * inv0, o1.y * inv0);
    }
    if (qr1 < NTOK) {
        *(float2*)&g_AO[(size_t)(b * NTOK + qr1) * DM + dbase] =
            make_float2(o0.z * inv1, o0.w * inv1);
        *(float2*)&g_AO[(size_t)(b * NTOK + qr1) * DM + dbase + 8] =
            make_float2(o1.z * inv1, o1.w * inv1);
    }
}

// ---------------------------------------------------------------------------
// Launch
// ---------------------------------------------------------------------------
extern "C" void kernel_launch(void* const* d_in, const int* in_sizes, int n_in,
                              void* d_out, int out_size) {
    const void* tok[3] = {0, 0, 0};
    const void* pos[4] = {0, 0, 0, 0};
    const void* wgt[4] = {0, 0, 0, 0};
    const void* wrpe = 0;
    int ntok = 0, npos = 0, nw = 0;
    for (int i = 0; i < n_in; i++) {
        int s = in_sizes[i];
        if (s == MTOT * DM && ntok < 3)      tok[ntok++] = d_in[i];
        else if (s == NTOK && npos < 4)      pos[npos++] = d_in[i];
        else if (s == DM * DM && nw < 4)     wgt[nw++]   = d_in[i];
        else if (s == NH * 32)               wrpe        = d_in[i];
    }
    if (ntok != 3 || npos != 4 || nw != 4 || !wrpe) {
        tok[0] = d_in[0]; tok[1] = d_in[1]; tok[2] = d_in[2];
        pos[0] = d_in[3]; pos[1] = d_in[4]; pos[2] = d_in[5]; pos[3] = d_in[6];
        int base = n_in - 5;
        wgt[0] = d_in[base]; wgt[1] = d_in[base + 1];
        wgt[2] = d_in[base + 2]; wgt[3] = d_in[base + 3];
        wrpe = d_in[base + 4];
    }
    float* out = (float*)d_out;

    // Raise dynamic smem cap for attn (idempotent; not an allocation)
    cudaFuncSetAttribute(attn_kernel,
                         cudaFuncAttributeMaxDynamicSharedMemorySize, DYN_BYTES);

    classify_kernel<<<1, 128>>>(
        (const float*)tok[0], (const float*)tok[1], (const float*)tok[2],
        (const int*)pos[0], (const int*)pos[1], (const int*)pos[2], (const int*)pos[3],
        (const float*)wgt[0], (const float*)wgt[1], (const float*)wgt[2], (const float*)wgt[3],
        (const float*)wrpe);

    bias_table_kernel<<<(NH * TBL + 255) / 256, 256>>>();

    // Build the full (h, q, k) bias matrix once — shared across all batches
    bias_mat_kernel<<<dim3(NTOK, NH), 256>>>();

    // fused QKV projection: blockIdx.z selects input (grid 4 x 63 x 3)
    gemm_big<<<dim3(DM / 64, MTOT / 128, 3), 256>>>(nullptr, 9);

    dim3 agrid((NTOK + 63) / 64, NH, BB);     // (16, 8, 8)
    attn_kernel<<<agrid, 256, DYN_BYTES>>>();

    gemm_big<<<dim3(DM / 64, MTOT / 128), 256>>>(out, 0);
}

// round 13
// speedup vs baseline: 1.0400x; 1.0400x over previous
#include <cuda_runtime.h>
#include <math.h>

// Problem constants (fixed by setup_inputs)
#define BB    8
#define NT    14
#define NF    72
#define NTOK  1008          // NT*NF
#define DM    256
#define NH    8
#define DK    32
#define NFREQ 8             // d_rpe/2/2
#define NDT   27            // 2*NT-1
#define NDF   143           // 2*NF-1
#define TBL   (NDT*NDF)     // 3861
#define MTOT  (BB*NTOK)     // 8064
#define BH    (BB*NH)       // 64
#define BROW  1024          // padded k-stride of g_B

// Scratch (device globals; module-static, no runtime allocation)
__device__ float g_table[NH * TBL];
__device__ float g_B[NH * NTOK * BROW];     // precomputed bias matrix, 33 MB
__device__ float g_Q[BH * NTOK * DK];
__device__ float g_K[BH * NTOK * DK];
__device__ float g_V[BH * NTOK * DK];
__device__ float g_AO[MTOT * DM];

// Resolved input pointers (filled by classify_kernel on device)
__device__ const float* dp_qt;
__device__ const float* dp_kt;
__device__ const float* dp_vt;
__device__ const int*   dp_tq;
__device__ const int*   dp_fq;
__device__ const int*   dp_tk;
__device__ const int*   dp_fk;
__device__ const float* dp_Wq;
__device__ const float* dp_Wk;
__device__ const float* dp_Wv;
__device__ const float* dp_Wo;
__device__ const float* dp_Wrpe;

// ---------------------------------------------------------------------------
// tf32 helpers
// ---------------------------------------------------------------------------
__device__ __forceinline__ unsigned tf32u(float f) {
    unsigned u;
    asm("cvt.rna.tf32.f32 %0, %1;" : "=r"(u) : "f"(f));
    return u;
}

__device__ __forceinline__ void mma_tf32(float4& d, unsigned a0, unsigned a1,
                                         unsigned a2, unsigned a3,
                                         unsigned b0, unsigned b1) {
    asm("mma.sync.aligned.m16n8k8.row.col.f32.tf32.tf32.f32 "
        "{%0,%1,%2,%3},{%4,%5,%6,%7},{%8,%9},{%0,%1,%2,%3};"
        : "+f"(d.x), "+f"(d.y), "+f"(d.z), "+f"(d.w)
        : "r"(a0), "r"(a1), "r"(a2), "r"(a3), "r"(b0), "r"(b1));
}

// ---------------------------------------------------------------------------
// 0) Classify inputs by content (ordering-agnostic).
// ---------------------------------------------------------------------------
__global__ void classify_kernel(const float* t0, const float* t1, const float* t2,
                                const int* p0, const int* p1, const int* p2, const int* p3,
                                const float* w0, const float* w1, const float* w2, const float* w3,
                                const float* wr) {
    __shared__ int mres[4];
    int tid = threadIdx.x;
    int w = tid >> 5, lane = tid & 31;
    const int* arr = (w == 0) ? p0 : (w == 1) ? p1 : (w == 2) ? p2 : p3;
    int m = 0;
    for (int i = lane; i < NTOK; i += 32) m = max(m, arr[i]);
#pragma unroll
    for (int off = 16; off > 0; off >>= 1)
        m = max(m, __shfl_xor_sync(0xffffffffu, m, off));
    if (lane == 0) mres[w] = m;
    __syncthreads();
    if (tid == 0) {
        bool T0 = (mres[0] <= NT - 1), T1 = (mres[1] <= NT - 1);
        bool T2 = (mres[2] <= NT - 1), T3 = (mres[3] <= NT - 1);
        if (!T0 && !T1 && T2 && T3) {
            dp_fk = p0; dp_fq = p1; dp_tk = p2; dp_tq = p3;
            dp_kt = t0; dp_qt = t1; dp_vt = t2;
            dp_Wk = w0; dp_Wo = w1; dp_Wq = w2; dp_Wv = w3;
        } else if (T0 && T1 && !T2 && !T3) {
            dp_tq = p0; dp_tk = p1; dp_fq = p2; dp_fk = p3;
            dp_qt = t0; dp_kt = t1; dp_vt = t2;
            dp_Wq = w0; dp_Wk = w1; dp_Wv = w2; dp_Wo = w3;
        } else {
            dp_tq = p0; dp_fq = p1; dp_tk = p2; dp_fk = p3;
            dp_qt = t0; dp_kt = t1; dp_vt = t2;
            dp_Wq = w0; dp_Wk = w1; dp_Wv = w2; dp_Wo = w3;
        }
        dp_Wrpe = wr;
    }
}

// ---------------------------------------------------------------------------
// 1) RPE bias table
// ---------------------------------------------------------------------------
__global__ void bias_table_kernel() {
    int gid = blockIdx.x * blockDim.x + threadIdx.x;
    if (gid >= NH * TBL) return;
    int pos = gid >> 3;
    int h   = gid & 7;
    int dt  = pos / NDF;
    int df  = pos % NDF;
    float pt = (float)(dt - (NT - 1)) / (float)(NT - 1);
    float pf = (float)(df - (NF - 1)) / (float)(NF - 1);
    const float* w = dp_Wrpe + h * 32;
    float acc = 0.f;
    float lg = logf(10000.0f);
#pragma unroll
    for (int j = 0; j < NFREQ; j++) {
        float fr = expf(-lg * (float)j / (float)NFREQ);
        float at = pt * fr;
        float af = pf * fr;
        acc += sinf(at) * w[j];
        acc += cosf(at) * w[NFREQ + j];
        acc += sinf(af) * w[2 * NFREQ + j];
        acc += cosf(af) * w[3 * NFREQ + j];
    }
    g_table[h * TBL + pos] = acc;
}

// ---------------------------------------------------------------------------
// 1b) Bias matrix: g_B[h][q][k] = table[h][...], done ONCE (shared by batches)
// ---------------------------------------------------------------------------
__global__ void bias_mat_kernel() {
    int q = blockIdx.x;
    int h = blockIdx.y;
    int base = (dp_tq[q] + NT - 1) * NDF + dp_fq[q] + NF - 1;
    const float* tb = g_table + h * TBL;
    float* dst = g_B + ((size_t)h * NTOK + q) * BROW;
    for (int k = threadIdx.x; k < NTOK; k += 256)
        dst[k] = tb[base - (dp_tk[k] * NDF + dp_fk[k])];
}

// ---------------------------------------------------------------------------
// 2) GEMM: 128x64 tiles, 8x4 micro, fp32 SIMT.
//    sel 9: fused QKV mode — blockIdx.z selects input 1/2/3.
//    sel 0: output projection, row-major write to outp.
// ---------------------------------------------------------------------------
__global__ void __launch_bounds__(256) gemm_big(float* __restrict__ outp, int sel) {
    if (sel == 9) sel = 1 + blockIdx.z;
    const float* X;
    const float* W;
    if      (sel == 1) { X = dp_qt; W = dp_Wq; }
    else if (sel == 2) { X = dp_kt; W = dp_Wk; }
    else if (sel == 3) { X = dp_vt; W = dp_Wv; }
    else               { X = g_AO;  W = dp_Wo; }

    __shared__ float As[16 * 132];
    __shared__ float Bs[16 * 68];
    int tid = threadIdx.x;
    int ca = tid & 15;
    int ra = tid >> 4;
    int m0 = blockIdx.y << 7;
    int n0 = blockIdx.x << 6;

    float acc[8][4];
#pragma unroll
    for (int i = 0; i < 8; i++)
#pragma unroll
        for (int j = 0; j < 4; j++) acc[i][j] = 0.f;

    for (int k0 = 0; k0 < DM; k0 += 16) {
        __syncthreads();
#pragma unroll
        for (int j = 0; j < 2; j++) {
            int f = tid + j * 256;
            int m = f >> 2, k4 = f & 3;
            float4 v = *(const float4*)(X + (size_t)(m0 + m) * DM + k0 + (k4 << 2));
            As[(k4 * 4 + 0) * 132 + m] = v.x;
            As[(k4 * 4 + 1) * 132 + m] = v.y;
            As[(k4 * 4 + 2) * 132 + m] = v.z;
            As[(k4 * 4 + 3) * 132 + m] = v.w;
        }
        {
            int n = tid >> 2, k4 = tid & 3;
            float4 v = *(const float4*)(W + (size_t)(n0 + n) * DM + k0 + (k4 << 2));
            Bs[(k4 * 4 + 0) * 68 + n] = v.x;
            Bs[(k4 * 4 + 1) * 68 + n] = v.y;
            Bs[(k4 * 4 + 2) * 68 + n] = v.z;
            Bs[(k4 * 4 + 3) * 68 + n] = v.w;
        }
        __syncthreads();
#pragma unroll
        for (int k = 0; k < 16; k++) {
            float4 a0 = *(const float4*)&As[k * 132 + (ra << 2)];
            float4 a1 = *(const float4*)&As[k * 132 + 64 + (ra << 2)];
            float4 b  = *(const float4*)&Bs[k * 68 + (ca << 2)];
            acc[0][0] += a0.x * b.x; acc[0][1] += a0.x * b.y; acc[0][2] += a0.x * b.z; acc[0][3] += a0.x * b.w;
            acc[1][0] += a0.y * b.x; acc[1][1] += a0.y * b.y; acc[1][2] += a0.y * b.z; acc[1][3] += a0.y * b.w;
            acc[2][0] += a0.z * b.x; acc[2][1] += a0.z * b.y; acc[2][2] += a0.z * b.z; acc[2][3] += a0.z * b.w;
            acc[3][0] += a0.w * b.x; acc[3][1] += a0.w * b.y; acc[3][2] += a0.w * b.z; acc[3][3] += a0.w * b.w;
            acc[4][0] += a1.x * b.x; acc[4][1] += a1.x * b.y; acc[4][2] += a1.x * b.z; acc[4][3] += a1.x * b.w;
            acc[5][0] += a1.y * b.x; acc[5][1] += a1.y * b.y; acc[5][2] += a1.y * b.z; acc[5][3] += a1.y * b.w;
            acc[6][0] += a1.z * b.x; acc[6][1] += a1.z * b.y; acc[6][2] += a1.z * b.z; acc[6][3] += a1.z * b.w;
            acc[7][0] += a1.w * b.x; acc[7][1] += a1.w * b.y; acc[7][2] += a1.w * b.z; acc[7][3] += a1.w * b.w;
        }
    }

    int ncol = n0 + (ca << 2);
    if (sel == 0) {
#pragma unroll
        for (int i = 0; i < 8; i++) {
            int m = m0 + ((i < 4) ? (ra * 4 + i) : (64 + ra * 4 + i - 4));
            float4 o = make_float4(acc[i][0], acc[i][1], acc[i][2], acc[i][3]);
            *(float4*)(outp + (size_t)m * DM + ncol) = o;
        }
    } else {
        float* dst = (sel == 1) ? g_Q : (sel == 2) ? g_K : g_V;
        int h = ncol >> 5;
        int d = ncol & 31;
#pragma unroll
        for (int i = 0; i < 8; i++) {
            int m = m0 + ((i < 4) ? (ra * 4 + i) : (64 + ra * 4 + i - 4));
            int b = m / NTOK;
            int nn = m - b * NTOK;
            float4 o = make_float4(acc[i][0], acc[i][1], acc[i][2], acc[i][3]);
            *(float4*)(dst + (size_t)((b * NH + h) * NTOK + nn) * DK + d) = o;
        }
    }
}

// ---------------------------------------------------------------------------
// 3) Flash attention: tf32 mma, max-free softmax, g_B coalesced bias,
//    NO register prefetch, 3 blocks/SM forced via launch bounds.
// ---------------------------------------------------------------------------
__global__ void __launch_bounds__(256, 3) attn_kernel() {
    __shared__ __align__(16) unsigned sPQ[64 * 68];
    __shared__ __align__(16) unsigned sKb[64 * 36];
    __shared__ __align__(16) unsigned sVb[64 * 40];
    __shared__ float sRedS[2][64];

    int tid = threadIdx.x;
    int lane = tid & 31;
    int w = tid >> 5;
    int wm = w >> 1;           // 0..3 -> q rows wm*16..+15
    int wn = w & 1;            // 0..1 -> key/dim half
    int r4 = lane >> 2;        // 0..7
    int cl = lane & 3;         // 0..3
    int q0 = blockIdx.x << 6;
    int h = blockIdx.y, b = blockIdx.z;
    int bh = b * NH + h;

    const float4* Q4 = (const float4*)(g_Q + (size_t)bh * NTOK * DK);
    const float4* K4 = (const float4*)(g_K + (size_t)bh * NTOK * DK);
    const float4* V4 = (const float4*)(g_V + (size_t)bh * NTOK * DK);

    // --- stage Q (scaled, tf32) into sPQ with stride 36 ---
    const float invs = 0.17677669529663688f;   // 1/sqrt(32)
#pragma unroll
    for (int j = 0; j < 2; j++) {
        int f = tid + j * 256;
        int r = f >> 3, c4 = f & 7;
        int qr = q0 + r;
        float4 v = make_float4(0.f, 0.f, 0.f, 0.f);
        if (qr < NTOK) v = Q4[qr * 8 + c4];
        unsigned* dst = &sPQ[r * 36 + (c4 << 2)];
        dst[0] = tf32u(v.x * invs);
        dst[1] = tf32u(v.y * invs);
        dst[2] = tf32u(v.z * invs);
        dst[3] = tf32u(v.w * invs);
    }
    __syncthreads();

    // --- extract Q fragments (held for all chunks) ---
    unsigned qf[4][4];
#pragma unroll
    for (int ks = 0; ks < 4; ks++) {
        int dc = ks * 8 + cl;
        qf[ks][0] = sPQ[(wm * 16 + r4) * 36 + dc];
        qf[ks][1] = sPQ[(wm * 16 + r4 + 8) * 36 + dc];
        qf[ks][2] = sPQ[(wm * 16 + r4) * 36 + dc + 4];
        qf[ks][3] = sPQ[(wm * 16 + r4 + 8) * 36 + dc + 4];
    }
    int row0 = wm * 16 + r4;
    int row1 = row0 + 8;
    const float* Bq0 = g_B + ((size_t)h * NTOK + min(q0 + row0, NTOK - 1)) * BROW;
    const float* Bq1 = g_B + ((size_t)h * NTOK + min(q0 + row1, NTOK - 1)) * BROW;

    float l0r = 0.f, l1r = 0.f;
    float4 o0 = make_float4(0.f, 0.f, 0.f, 0.f);
    float4 o1 = make_float4(0.f, 0.f, 0.f, 0.f);

    int pr = tid >> 3;             // KV load row 0..31 (j=0) / +32 (j=1)
    int pc4 = tid & 7;             // KV load col group

    for (int kc = 0; kc < 16; kc++) {
        int k0 = kc << 6;

        // --- bias loads (register-only; overlap the barrier drain) ---
        float2 b0v[4], b1v[4];
#pragma unroll
        for (int nt = 0; nt < 4; nt++) {
            int col = k0 + wn * 32 + nt * 8 + 2 * cl;   // < 1024 (padded row)
            b0v[nt] = *(const float2*)(Bq0 + col);
            b1v[nt] = *(const float2*)(Bq1 + col);
        }

        __syncthreads();   // prior chunk readers done before KV overwrite
        // --- load + convert + store this chunk's KV ---
#pragma unroll
        for (int j = 0; j < 2; j++) {
            int kr = k0 + pr + j * 32;
            float4 kv = make_float4(0.f, 0.f, 0.f, 0.f);
            float4 vv = make_float4(0.f, 0.f, 0.f, 0.f);
            if (kr < NTOK) {
                kv = K4[kr * 8 + pc4];
                vv = V4[kr * 8 + pc4];
            }
            int r = pr + j * 32;
            unsigned* dk = &sKb[r * 36 + (pc4 << 2)];
            dk[0] = tf32u(kv.x); dk[1] = tf32u(kv.y);
            dk[2] = tf32u(kv.z); dk[3] = tf32u(kv.w);
            unsigned* dv = &sVb[r * 40 + (pc4 << 2)];
            dv[0] = tf32u(vv.x); dv[1] = tf32u(vv.y);
            dv[2] = tf32u(vv.z); dv[3] = tf32u(vv.w);
        }
        __syncthreads();

        // --- scores: S = Q K^T (per warp: 16q x 32k) ---
        float4 c[4];
#pragma unroll
        for (int nt = 0; nt < 4; nt++) c[nt] = make_float4(0.f, 0.f, 0.f, 0.f);
#pragma unroll
        for (int nt = 0; nt < 4; nt++) {
            int key = wn * 32 + nt * 8 + r4;
#pragma unroll
            for (int ks = 0; ks < 4; ks++) {
                int dd = ks * 8 + cl;
                unsigned b0 = sKb[key * 36 + dd];
                unsigned b1 = sKb[key * 36 + dd + 4];
                mma_tf32(c[nt], qf[ks][0], qf[ks][1], qf[ks][2], qf[ks][3], b0, b1);
            }
        }

        // --- bias + exp (max-free) + partial sums + write P ---
        int rem = NTOK - k0;
#pragma unroll
        for (int nt = 0; nt < 4; nt++) {
            int col0 = wn * 32 + nt * 8 + 2 * cl;
            bool v0 = col0 < rem, v1 = col0 + 1 < rem;
            c[nt].x = v0 ? __expf(c[nt].x + b0v[nt].x) : 0.f;
            c[nt].y = v1 ? __expf(c[nt].y + b0v[nt].y) : 0.f;
            c[nt].z = v0 ? __expf(c[nt].z + b1v[nt].x) : 0.f;
            c[nt].w = v1 ? __expf(c[nt].w + b1v[nt].y) : 0.f;
            l0r += c[nt].x + c[nt].y;
            l1r += c[nt].z + c[nt].w;
            uint2 pa; pa.x = tf32u(c[nt].x); pa.y = tf32u(c[nt].y);
            uint2 pb; pb.x = tf32u(c[nt].z); pb.y = tf32u(c[nt].w);
            *(uint2*)&sPQ[row0 * 68 + col0] = pa;
            *(uint2*)&sPQ[row1 * 68 + col0] = pb;
        }
        __syncthreads();

        // --- PV: O += P V (per warp: 16q x 16d) ---
#pragma unroll
        for (int ks = 0; ks < 8; ks++) {
            int kcidx = ks * 8 + cl;
            unsigned a0 = sPQ[row0 * 68 + kcidx];
            unsigned a1 = sPQ[row1 * 68 + kcidx];
            unsigned a2 = sPQ[row0 * 68 + kcidx + 4];
            unsigned a3 = sPQ[row1 * 68 + kcidx + 4];
            {
                int dcol = wn * 16 + r4;
                unsigned b0 = sVb[kcidx * 40 + dcol];
                unsigned b1 = sVb[(kcidx + 4) * 40 + dcol];
                mma_tf32(o0, a0, a1, a2, a3, b0, b1);
            }
            {
                int dcol = wn * 16 + 8 + r4;
                unsigned b0 = sVb[kcidx * 40 + dcol];
                unsigned b1 = sVb[(kcidx + 4) * 40 + dcol];
                mma_tf32(o1, a0, a1, a2, a3, b0, b1);
            }
        }
    }

    // --- epilogue: one-time row-sum reduction, then normalize & store ---
    l0r += __shfl_xor_sync(0xffffffffu, l0r, 1);
    l0r += __shfl_xor_sync(0xffffffffu, l0r, 2);
    l1r += __shfl_xor_sync(0xffffffffu, l1r, 1);
    l1r += __shfl_xor_sync(0xffffffffu, l1r, 2);
    if (cl == 0) {
        sRedS[wn][row0] = l0r;
        sRedS[wn][row1] = l1r;
    }
    __syncthreads();
    float inv0 = 1.0f / (sRedS[0][row0] + sRedS[1][row0]);
    float inv1 = 1.0f / (sRedS[0][row1] + sRedS[1][row1]);

    int qr0 = q0 + row0, qr1 = q0 + row1;
    int dbase = h * DK + wn * 16 + 2 * cl;
    if (qr0 < NTOK) {
        *(float2*)&g_AO[(size_t)(b * NTOK + qr0) * DM + dbase] =
            make_float2(o0.x * inv0, o0.y * inv0);
        *(float2*)&g_AO[(size_t)(b * NTOK + qr0) * DM + dbase + 8] =
            make_float2(o1.x * inv0, o1.y * inv0);
    }
    if (qr1 < NTOK) {
        *(float2*)&g_AO[(size_t)(b * NTOK + qr1) * DM + dbase] =
            make_float2(o0.z * inv1, o0.w * inv1);
        *(float2*)&g_AO[(size_t)(b * NTOK + qr1) * DM + dbase + 8] =
            make_float2(o1.z * inv1, o1.w * inv1);
    }
}

// ---------------------------------------------------------------------------
// Launch
// ---------------------------------------------------------------------------
extern "C" void kernel_launch(void* const* d_in, const int* in_sizes, int n_in,
                              void* d_out, int out_size) {
    const void* tok[3] = {0, 0, 0};
    const void* pos[4] = {0, 0, 0, 0};
    const void* wgt[4] = {0, 0, 0, 0};
    const void* wrpe = 0;
    int ntok = 0, npos = 0, nw = 0;
    for (int i = 0; i < n_in; i++) {
        int s = in_sizes[i];
        if (s == MTOT * DM && ntok < 3)      tok[ntok++] = d_in[i];
        else if (s == NTOK && npos < 4)      pos[npos++] = d_in[i];
        else if (s == DM * DM && nw < 4)     wgt[nw++]   = d_in[i];
        else if (s == NH * 32)               wrpe        = d_in[i];
    }
    if (ntok != 3 || npos != 4 || nw != 4 || !wrpe) {
        tok[0] = d_in[0]; tok[1] = d_in[1]; tok[2] = d_in[2];
        pos[0] = d_in[3]; pos[1] = d_in[4]; pos[2] = d_in[5]; pos[3] = d_in[6];
        int base = n_in - 5;
        wgt[0] = d_in[base]; wgt[1] = d_in[base + 1];
        wgt[2] = d_in[base + 2]; wgt[3] = d_in[base + 3];
        wrpe = d_in[base + 4];
    }
    float* out = (float*)d_out;

    classify_kernel<<<1, 128>>>(
        (const float*)tok[0], (const float*)tok[1], (const float*)tok[2],
        (const int*)pos[0], (const int*)pos[1], (const int*)pos[2], (const int*)pos[3],
        (const float*)wgt[0], (const float*)wgt[1], (const float*)wgt[2], (const float*)wgt[3],
        (const float*)wrpe);

    bias_table_kernel<<<(NH * TBL + 255) / 256, 256>>>();

    // Build the full (h, q, k) bias matrix once — shared across all batches
    bias_mat_kernel<<<dim3(NTOK, NH), 256>>>();

    // fused QKV projection: blockIdx.z selects input (grid 4 x 63 x 3)
    gemm_big<<<dim3(DM / 64, MTOT / 128, 3), 256>>>(nullptr, 9);

    dim3 agrid((NTOK + 63) / 64, NH, BB);     // (16, 8, 8)
    attn_kernel<<<agrid, 256>>>();

    gemm_big<<<dim3(DM / 64, MTOT / 128), 256>>>(out, 0);
}

// round 14
// speedup vs baseline: 1.0731x; 1.0318x over previous
#include <cuda_runtime.h>
#include <cuda_fp16.h>
#include <math.h>

// Problem constants (fixed by setup_inputs)
#define BB    8
#define NT    14
#define NF    72
#define NTOK  1008          // NT*NF
#define DM    256
#define NH    8
#define DK    32
#define NFREQ 8             // d_rpe/2/2
#define NDT   27            // 2*NT-1
#define NDF   143           // 2*NF-1
#define TBL   (NDT*NDF)     // 3861
#define MTOT  (BB*NTOK)     // 8064
#define BH    (BB*NH)       // 64
#define BROW  1024          // padded k-stride of g_B

// Scratch (device globals; module-static, no runtime allocation)
__device__ float g_table[NH * TBL];
__device__ float g_B[NH * NTOK * BROW];     // precomputed bias matrix, 33 MB
__device__ float g_Q[BH * NTOK * DK];
__device__ float g_K[BH * NTOK * DK];
__device__ float g_V[BH * NTOK * DK];
__device__ float g_AO[MTOT * DM];

// Resolved input pointers (filled by classify_kernel on device)
__device__ const float* dp_qt;
__device__ const float* dp_kt;
__device__ const float* dp_vt;
__device__ const int*   dp_tq;
__device__ const int*   dp_fq;
__device__ const int*   dp_tk;
__device__ const int*   dp_fk;
__device__ const float* dp_Wq;
__device__ const float* dp_Wk;
__device__ const float* dp_Wv;
__device__ const float* dp_Wo;
__device__ const float* dp_Wrpe;

// ---------------------------------------------------------------------------
// mma helpers
// ---------------------------------------------------------------------------
__device__ __forceinline__ unsigned tf32u(float f) {
    unsigned u;
    asm("cvt.rna.tf32.f32 %0, %1;" : "=r"(u) : "f"(f));
    return u;
}

__device__ __forceinline__ unsigned packh2(float a, float b) {
    __half2 h = __floats2half2_rn(a, b);   // low = a, high = b
    return *(unsigned*)&h;
}

__device__ __forceinline__ void mma_tf32(float4& d, unsigned a0, unsigned a1,
                                         unsigned a2, unsigned a3,
                                         unsigned b0, unsigned b1) {
    asm("mma.sync.aligned.m16n8k8.row.col.f32.tf32.tf32.f32 "
        "{%0,%1,%2,%3},{%4,%5,%6,%7},{%8,%9},{%0,%1,%2,%3};"
        : "+f"(d.x), "+f"(d.y), "+f"(d.z), "+f"(d.w)
        : "r"(a0), "r"(a1), "r"(a2), "r"(a3), "r"(b0), "r"(b1));
}

__device__ __forceinline__ void mma_f16(float4& d, unsigned a0, unsigned a1,
                                        unsigned a2, unsigned a3,
                                        unsigned b0, unsigned b1) {
    asm("mma.sync.aligned.m16n8k16.row.col.f32.f16.f16.f32 "
        "{%0,%1,%2,%3},{%4,%5,%6,%7},{%8,%9},{%0,%1,%2,%3};"
        : "+f"(d.x), "+f"(d.y), "+f"(d.z), "+f"(d.w)
        : "r"(a0), "r"(a1), "r"(a2), "r"(a3), "r"(b0), "r"(b1));
}

// ---------------------------------------------------------------------------
// 0) Classify inputs by content (ordering-agnostic).
// ---------------------------------------------------------------------------
__global__ void classify_kernel(const float* t0, const float* t1, const float* t2,
                                const int* p0, const int* p1, const int* p2, const int* p3,
                                const float* w0, const float* w1, const float* w2, const float* w3,
                                const float* wr) {
    __shared__ int mres[4];
    int tid = threadIdx.x;
    int w = tid >> 5, lane = tid & 31;
    const int* arr = (w == 0) ? p0 : (w == 1) ? p1 : (w == 2) ? p2 : p3;
    int m = 0;
    for (int i = lane; i < NTOK; i += 32) m = max(m, arr[i]);
#pragma unroll
    for (int off = 16; off > 0; off >>= 1)
        m = max(m, __shfl_xor_sync(0xffffffffu, m, off));
    if (lane == 0) mres[w] = m;
    __syncthreads();
    if (tid == 0) {
        bool T0 = (mres[0] <= NT - 1), T1 = (mres[1] <= NT - 1);
        bool T2 = (mres[2] <= NT - 1), T3 = (mres[3] <= NT - 1);
        if (!T0 && !T1 && T2 && T3) {
            dp_fk = p0; dp_fq = p1; dp_tk = p2; dp_tq = p3;
            dp_kt = t0; dp_qt = t1; dp_vt = t2;
            dp_Wk = w0; dp_Wo = w1; dp_Wq = w2; dp_Wv = w3;
        } else if (T0 && T1 && !T2 && !T3) {
            dp_tq = p0; dp_tk = p1; dp_fq = p2; dp_fk = p3;
            dp_qt = t0; dp_kt = t1; dp_vt = t2;
            dp_Wq = w0; dp_Wk = w1; dp_Wv = w2; dp_Wo = w3;
        } else {
            dp_tq = p0; dp_fq = p1; dp_tk = p2; dp_fk = p3;
            dp_qt = t0; dp_kt = t1; dp_vt = t2;
            dp_Wq = w0; dp_Wk = w1; dp_Wv = w2; dp_Wo = w3;
        }
        dp_Wrpe = wr;
    }
}

// ---------------------------------------------------------------------------
// 1) RPE bias table
// ---------------------------------------------------------------------------
__global__ void bias_table_kernel() {
    int gid = blockIdx.x * blockDim.x + threadIdx.x;
    if (gid >= NH * TBL) return;
    int pos = gid >> 3;
    int h   = gid & 7;
    int dt  = pos / NDF;
    int df  = pos % NDF;
    float pt = (float)(dt - (NT - 1)) / (float)(NT - 1);
    float pf = (float)(df - (NF - 1)) / (float)(NF - 1);
    const float* w = dp_Wrpe + h * 32;
    float acc = 0.f;
    float lg = logf(10000.0f);
#pragma unroll
    for (int j = 0; j < NFREQ; j++) {
        float fr = expf(-lg * (float)j / (float)NFREQ);
        float at = pt * fr;
        float af = pf * fr;
        acc += sinf(at) * w[j];
        acc += cosf(at) * w[NFREQ + j];
        acc += sinf(af) * w[2 * NFREQ + j];
        acc += cosf(af) * w[3 * NFREQ + j];
    }
    g_table[h * TBL + pos] = acc;
}

// ---------------------------------------------------------------------------
// 1b) Bias matrix: g_B[h][q][k] = table[h][...], done ONCE (shared by batches)
// ---------------------------------------------------------------------------
__global__ void bias_mat_kernel() {
    int q = blockIdx.x;
    int h = blockIdx.y;
    int base = (dp_tq[q] + NT - 1) * NDF + dp_fq[q] + NF - 1;
    const float* tb = g_table + h * TBL;
    float* dst = g_B + ((size_t)h * NTOK + q) * BROW;
    for (int k = threadIdx.x; k < NTOK; k += 256)
        dst[k] = tb[base - (dp_tk[k] * NDF + dp_fk[k])];
}

// ---------------------------------------------------------------------------
// 2) GEMM: 128x64 tiles, 8x4 micro, fp32 SIMT.
//    sel 9: fused QKV mode — blockIdx.z selects input 1/2/3.
//    sel 0: output projection, row-major write to outp.
// ---------------------------------------------------------------------------
__global__ void __launch_bounds__(256) gemm_big(float* __restrict__ outp, int sel) {
    if (sel == 9) sel = 1 + blockIdx.z;
    const float* X;
    const float* W;
    if      (sel == 1) { X = dp_qt; W = dp_Wq; }
    else if (sel == 2) { X = dp_kt; W = dp_Wk; }
    else if (sel == 3) { X = dp_vt; W = dp_Wv; }
    else               { X = g_AO;  W = dp_Wo; }

    __shared__ float As[16 * 132];
    __shared__ float Bs[16 * 68];
    int tid = threadIdx.x;
    int ca = tid & 15;
    int ra = tid >> 4;
    int m0 = blockIdx.y << 7;
    int n0 = blockIdx.x << 6;

    float acc[8][4];
#pragma unroll
    for (int i = 0; i < 8; i++)
#pragma unroll
        for (int j = 0; j < 4; j++) acc[i][j] = 0.f;

    for (int k0 = 0; k0 < DM; k0 += 16) {
        __syncthreads();
#pragma unroll
        for (int j = 0; j < 2; j++) {
            int f = tid + j * 256;
            int m = f >> 2, k4 = f & 3;
            float4 v = *(const float4*)(X + (size_t)(m0 + m) * DM + k0 + (k4 << 2));
            As[(k4 * 4 + 0) * 132 + m] = v.x;
            As[(k4 * 4 + 1) * 132 + m] = v.y;
            As[(k4 * 4 + 2) * 132 + m] = v.z;
            As[(k4 * 4 + 3) * 132 + m] = v.w;
        }
        {
            int n = tid >> 2, k4 = tid & 3;
            float4 v = *(const float4*)(W + (size_t)(n0 + n) * DM + k0 + (k4 << 2));
            Bs[(k4 * 4 + 0) * 68 + n] = v.x;
            Bs[(k4 * 4 + 1) * 68 + n] = v.y;
            Bs[(k4 * 4 + 2) * 68 + n] = v.z;
            Bs[(k4 * 4 + 3) * 68 + n] = v.w;
        }
        __syncthreads();
#pragma unroll
        for (int k = 0; k < 16; k++) {
            float4 a0 = *(const float4*)&As[k * 132 + (ra << 2)];
            float4 a1 = *(const float4*)&As[k * 132 + 64 + (ra << 2)];
            float4 b  = *(const float4*)&Bs[k * 68 + (ca << 2)];
            acc[0][0] += a0.x * b.x; acc[0][1] += a0.x * b.y; acc[0][2] += a0.x * b.z; acc[0][3] += a0.x * b.w;
            acc[1][0] += a0.y * b.x; acc[1][1] += a0.y * b.y; acc[1][2] += a0.y * b.z; acc[1][3] += a0.y * b.w;
            acc[2][0] += a0.z * b.x; acc[2][1] += a0.z * b.y; acc[2][2] += a0.z * b.z; acc[2][3] += a0.z * b.w;
            acc[3][0] += a0.w * b.x; acc[3][1] += a0.w * b.y; acc[3][2] += a0.w * b.z; acc[3][3] += a0.w * b.w;
            acc[4][0] += a1.x * b.x; acc[4][1] += a1.x * b.y; acc[4][2] += a1.x * b.z; acc[4][3] += a1.x * b.w;
            acc[5][0] += a1.y * b.x; acc[5][1] += a1.y * b.y; acc[5][2] += a1.y * b.z; acc[5][3] += a1.y * b.w;
            acc[6][0] += a1.z * b.x; acc[6][1] += a1.z * b.y; acc[6][2] += a1.z * b.z; acc[6][3] += a1.z * b.w;
            acc[7][0] += a1.w * b.x; acc[7][1] += a1.w * b.y; acc[7][2] += a1.w * b.z; acc[7][3] += a1.w * b.w;
        }
    }

    int ncol = n0 + (ca << 2);
    if (sel == 0) {
#pragma unroll
        for (int i = 0; i < 8; i++) {
            int m = m0 + ((i < 4) ? (ra * 4 + i) : (64 + ra * 4 + i - 4));
            float4 o = make_float4(acc[i][0], acc[i][1], acc[i][2], acc[i][3]);
            *(float4*)(outp + (size_t)m * DM + ncol) = o;
        }
    } else {
        float* dst = (sel == 1) ? g_Q : (sel == 2) ? g_K : g_V;
        int h = ncol >> 5;
        int d = ncol & 31;
#pragma unroll
        for (int i = 0; i < 8; i++) {
            int m = m0 + ((i < 4) ? (ra * 4 + i) : (64 + ra * 4 + i - 4));
            int b = m / NTOK;
            int nn = m - b * NTOK;
            float4 o = make_float4(acc[i][0], acc[i][1], acc[i][2], acc[i][3]);
            *(float4*)(dst + (size_t)((b * NH + h) * NTOK + nn) * DK + d) = o;
        }
    }
}

// ---------------------------------------------------------------------------
// 3) Flash attention: QK in fp16 m16n8k16 (half the mmas + half the K bytes),
//    PV in tf32 (proven), max-free softmax, g_B coalesced bias, occ 3.
// ---------------------------------------------------------------------------
__global__ void __launch_bounds__(256, 3) attn_kernel() {
    __shared__ __align__(16) unsigned sPQ[64 * 68];  // Q staging (stride 20) then P (stride 68)
    __shared__ __align__(16) unsigned sKh[64 * 20];  // K as half2 pairs, stride 20 words
    __shared__ __align__(16) unsigned sVb[64 * 40];  // V tf32, stride 40
    __shared__ float sRedS[2][64];

    int tid = threadIdx.x;
    int lane = tid & 31;
    int w = tid >> 5;
    int wm = w >> 1;           // 0..3 -> q rows wm*16..+15
    int wn = w & 1;            // 0..1 -> key/dim half
    int r4 = lane >> 2;        // 0..7
    int cl = lane & 3;         // 0..3
    int q0 = blockIdx.x << 6;
    int h = blockIdx.y, b = blockIdx.z;
    int bh = b * NH + h;

    const float4* Q4 = (const float4*)(g_Q + (size_t)bh * NTOK * DK);
    const float4* K4 = (const float4*)(g_K + (size_t)bh * NTOK * DK);
    const float4* V4 = (const float4*)(g_V + (size_t)bh * NTOK * DK);

    // --- stage Q (scaled) as packed half2, stride 20 words ---
    const float invs = 0.17677669529663688f;   // 1/sqrt(32)
#pragma unroll
    for (int j = 0; j < 2; j++) {
        int f = tid + j * 256;
        int r = f >> 3, c4 = f & 7;
        int qr = q0 + r;
        float4 v = make_float4(0.f, 0.f, 0.f, 0.f);
        if (qr < NTOK) v = Q4[qr * 8 + c4];
        uint2 qw;
        qw.x = packh2(v.x * invs, v.y * invs);
        qw.y = packh2(v.z * invs, v.w * invs);
        *(uint2*)&sPQ[r * 20 + 2 * c4] = qw;
    }
    __syncthreads();

    // --- extract Q fp16 fragments (held for all chunks): 2 ks x 4 regs ---
    int row0 = wm * 16 + r4;
    int row1 = row0 + 8;
    unsigned qf[2][4];
#pragma unroll
    for (int ks = 0; ks < 2; ks++) {
        int wd = ks * 8 + cl;
        qf[ks][0] = sPQ[row0 * 20 + wd];
        qf[ks][1] = sPQ[row1 * 20 + wd];
        qf[ks][2] = sPQ[row0 * 20 + wd + 4];
        qf[ks][3] = sPQ[row1 * 20 + wd + 4];
    }
    const float* Bq0 = g_B + ((size_t)h * NTOK + min(q0 + row0, NTOK - 1)) * BROW;
    const float* Bq1 = g_B + ((size_t)h * NTOK + min(q0 + row1, NTOK - 1)) * BROW;

    float l0r = 0.f, l1r = 0.f;
    float4 o0 = make_float4(0.f, 0.f, 0.f, 0.f);
    float4 o1 = make_float4(0.f, 0.f, 0.f, 0.f);

    int pr = tid >> 3;             // KV load row 0..31 (j=0) / +32 (j=1)
    int pc4 = tid & 7;             // KV load col group

    for (int kc = 0; kc < 16; kc++) {
        int k0 = kc << 6;

        // --- bias loads (register-only; overlap the barrier drain) ---
        float2 b0v[4], b1v[4];
#pragma unroll
        for (int nt = 0; nt < 4; nt++) {
            int col = k0 + wn * 32 + nt * 8 + 2 * cl;   // < 1024 (padded row)
            b0v[nt] = *(const float2*)(Bq0 + col);
            b1v[nt] = *(const float2*)(Bq1 + col);
        }

        __syncthreads();   // prior chunk readers done before KV overwrite
        // --- load + convert + store this chunk's KV ---
#pragma unroll
        for (int j = 0; j < 2; j++) {
            int kr = k0 + pr + j * 32;
            float4 kv = make_float4(0.f, 0.f, 0.f, 0.f);
            float4 vv = make_float4(0.f, 0.f, 0.f, 0.f);
            if (kr < NTOK) {
                kv = K4[kr * 8 + pc4];
                vv = V4[kr * 8 + pc4];
            }
            int r = pr + j * 32;
            uint2 kw;
            kw.x = packh2(kv.x, kv.y);
            kw.y = packh2(kv.z, kv.w);
            *(uint2*)&sKh[r * 20 + 2 * pc4] = kw;
            unsigned* dv = &sVb[r * 40 + (pc4 << 2)];
            dv[0] = tf32u(vv.x); dv[1] = tf32u(vv.y);
            dv[2] = tf32u(vv.z); dv[3] = tf32u(vv.w);
        }
        __syncthreads();

        // --- scores: S = Q K^T, fp16 m16n8k16 (per warp: 16q x 32k, 8 mmas) ---
        float4 c[4];
#pragma unroll
        for (int nt = 0; nt < 4; nt++) c[nt] = make_float4(0.f, 0.f, 0.f, 0.f);
#pragma unroll
        for (int nt = 0; nt < 4; nt++) {
            int kb = (wn * 32 + nt * 8 + r4) * 20;
#pragma unroll
            for (int ks = 0; ks < 2; ks++) {
                int wd = ks * 8 + cl;
                unsigned b0 = sKh[kb + wd];
                unsigned b1 = sKh[kb + wd + 4];
                mma_f16(c[nt], qf[ks][0], qf[ks][1], qf[ks][2], qf[ks][3], b0, b1);
            }
        }

        // --- bias + exp (max-free) + partial sums + write P (tf32 pairs) ---
        int rem = NTOK - k0;
#pragma unroll
        for (int nt = 0; nt < 4; nt++) {
            int col0 = wn * 32 + nt * 8 + 2 * cl;
            bool v0 = col0 < rem, v1 = col0 + 1 < rem;
            c[nt].x = v0 ? __expf(c[nt].x + b0v[nt].x) : 0.f;
            c[nt].y = v1 ? __expf(c[nt].y + b0v[nt].y) : 0.f;
            c[nt].z = v0 ? __expf(c[nt].z + b1v[nt].x) : 0.f;
            c[nt].w = v1 ? __expf(c[nt].w + b1v[nt].y) : 0.f;
            l0r += c[nt].x + c[nt].y;
            l1r += c[nt].z + c[nt].w;
            uint2 pa; pa.x = tf32u(c[nt].x); pa.y = tf32u(c[nt].y);
            uint2 pb; pb.x = tf32u(c[nt].z); pb.y = tf32u(c[nt].w);
            *(uint2*)&sPQ[row0 * 68 + col0] = pa;
            *(uint2*)&sPQ[row1 * 68 + col0] = pb;
        }
        __syncthreads();

        // --- PV: O += P V, tf32 (per warp: 16q x 16d) ---
#pragma unroll
        for (int ks = 0; ks < 8; ks++) {
            int kcidx = ks * 8 + cl;
            unsigned a0 = sPQ[row0 * 68 + kcidx];
            unsigned a1 = sPQ[row1 * 68 + kcidx];
            unsigned a2 = sPQ[row0 * 68 + kcidx + 4];
            unsigned a3 = sPQ[row1 * 68 + kcidx + 4];
            {
                int dcol = wn * 16 + r4;
                unsigned b0 = sVb[kcidx * 40 + dcol];
                unsigned b1 = sVb[(kcidx + 4) * 40 + dcol];
                mma_tf32(o0, a0, a1, a2, a3, b0, b1);
            }
            {
                int dcol = wn * 16 + 8 + r4;
                unsigned b0 = sVb[kcidx * 40 + dcol];
                unsigned b1 = sVb[(kcidx + 4) * 40 + dcol];
                mma_tf32(o1, a0, a1, a2, a3, b0, b1);
            }
        }
    }

    // --- epilogue: one-time row-sum reduction, then normalize & store ---
    l0r += __shfl_xor_sync(0xffffffffu, l0r, 1);
    l0r += __shfl_xor_sync(0xffffffffu, l0r, 2);
    l1r += __shfl_xor_sync(0xffffffffu, l1r, 1);
    l1r += __shfl_xor_sync(0xffffffffu, l1r, 2);
    if (cl == 0) {
        sRedS[wn][row0] = l0r;
        sRedS[wn][row1] = l1r;
    }
    __syncthreads();
    float inv0 = 1.0f / (sRedS[0][row0] + sRedS[1][row0]);
    float inv1 = 1.0f / (sRedS[0][row1] + sRedS[1][row1]);

    int qr0 = q0 + row0, qr1 = q0 + row1;
    int dbase = h * DK + wn * 16 + 2 * cl;
    if (qr0 < NTOK) {
        *(float2*)&g_AO[(size_t)(b * NTOK + qr0) * DM + dbase] =
            make_float2(o0.x * inv0, o0.y * inv0);
        *(float2*)&g_AO[(size_t)(b * NTOK + qr0) * DM + dbase + 8] =
            make_float2(o1.x * inv0, o1.y * inv0);
    }
    if (qr1 < NTOK) {
        *(float2*)&g_AO[(size_t)(b * NTOK + qr1) * DM + dbase] =
            make_float2(o0.z * inv1, o0.w * inv1);
        *(float2*)&g_AO[(size_t)(b * NTOK + qr1) * DM + dbase + 8] =
            make_float2(o1.z * inv1, o1.w * inv1);
    }
}

// ---------------------------------------------------------------------------
// Launch
// ---------------------------------------------------------------------------
extern "C" void kernel_launch(void* const* d_in, const int* in_sizes, int n_in,
                              void* d_out, int out_size) {
    const void* tok[3] = {0, 0, 0};
    const void* pos[4] = {0, 0, 0, 0};
    const void* wgt[4] = {0, 0, 0, 0};
    const void* wrpe = 0;
    int ntok = 0, npos = 0, nw = 0;
    for (int i = 0; i < n_in; i++) {
        int s = in_sizes[i];
        if (s == MTOT * DM && ntok < 3)      tok[ntok++] = d_in[i];
        else if (s == NTOK && npos < 4)      pos[npos++] = d_in[i];
        else if (s == DM * DM && nw < 4)     wgt[nw++]   = d_in[i];
        else if (s == NH * 32)               wrpe        = d_in[i];
    }
    if (ntok != 3 || npos != 4 || nw != 4 || !wrpe) {
        tok[0] = d_in[0]; tok[1] = d_in[1]; tok[2] = d_in[2];
        pos[0] = d_in[3]; pos[1] = d_in[4]; pos[2] = d_in[5]; pos[3] = d_in[6];
        int base = n_in - 5;
        wgt[0] = d_in[base]; wgt[1] = d_in[base + 1];
        wgt[2] = d_in[base + 2]; wgt[3] = d_in[base + 3];
        wrpe = d_in[base + 4];
    }
    float* out = (float*)d_out;

    classify_kernel<<<1, 128>>>(
        (const float*)tok[0], (const float*)tok[1], (const float*)tok[2],
        (const int*)pos[0], (const int*)pos[1], (const int*)pos[2], (const int*)pos[3],
        (const float*)wgt[0], (const float*)wgt[1], (const float*)wgt[2], (const float*)wgt[3],
        (const float*)wrpe);

    bias_table_kernel<<<(NH * TBL + 255) / 256, 256>>>();

    // Build the full (h, q, k) bias matrix once — shared across all batches
    bias_mat_kernel<<<dim3(NTOK, NH), 256>>>();

    // fused QKV projection: blockIdx.z selects input (grid 4 x 63 x 3)
    gemm_big<<<dim3(DM / 64, MTOT / 128, 3), 256>>>(nullptr, 9);

    dim3 agrid((NTOK + 63) / 64, NH, BB);     // (16, 8, 8)
    attn_kernel<<<agrid, 256>>>();

    gemm_big<<<dim3(DM / 64, MTOT / 128), 256>>>(out, 0);
}

// round 15
// speedup vs baseline: 1.1086x; 1.0331x over previous
#include <cuda_runtime.h>
#include <cuda_fp16.h>
#include <math.h>

// Problem constants (fixed by setup_inputs)
#define BB    8
#define NT    14
#define NF    72
#define NTOK  1008          // NT*NF
#define DM    256
#define NH    8
#define DK    32
#define NFREQ 8             // d_rpe/2/2
#define NDT   27            // 2*NT-1
#define NDF   143           // 2*NF-1
#define TBL   (NDT*NDF)     // 3861
#define MTOT  (BB*NTOK)     // 8064
#define BH    (BB*NH)       // 64
#define BROW  1024          // padded k-stride of g_B

// Scratch (device globals; module-static, no runtime allocation)
__device__ float g_table[NH * TBL];
__device__ float g_B[NH * NTOK * BROW];     // precomputed bias matrix, 33 MB
__device__ float g_Q[BH * NTOK * DK];
__device__ float g_K[BH * NTOK * DK];
__device__ float g_V[BH * NTOK * DK];
__device__ float g_AO[MTOT * DM];

// Resolved input pointers (filled by classify_kernel on device)
__device__ const float* dp_qt;
__device__ const float* dp_kt;
__device__ const float* dp_vt;
__device__ const int*   dp_tq;
__device__ const int*   dp_fq;
__device__ const int*   dp_tk;
__device__ const int*   dp_fk;
__device__ const float* dp_Wq;
__device__ const float* dp_Wk;
__device__ const float* dp_Wv;
__device__ const float* dp_Wo;
__device__ const float* dp_Wrpe;

// ---------------------------------------------------------------------------
// mma helpers
// ---------------------------------------------------------------------------
__device__ __forceinline__ unsigned packh2(float a, float b) {
    __half2 h = __floats2half2_rn(a, b);   // low = a, high = b
    return *(unsigned*)&h;
}

__device__ __forceinline__ void mma_f16(float4& d, unsigned a0, unsigned a1,
                                        unsigned a2, unsigned a3,
                                        unsigned b0, unsigned b1) {
    asm("mma.sync.aligned.m16n8k16.row.col.f32.f16.f16.f32 "
        "{%0,%1,%2,%3},{%4,%5,%6,%7},{%8,%9},{%0,%1,%2,%3};"
        : "+f"(d.x), "+f"(d.y), "+f"(d.z), "+f"(d.w)
        : "r"(a0), "r"(a1), "r"(a2), "r"(a3), "r"(b0), "r"(b1));
}

// ---------------------------------------------------------------------------
// 0) Classify inputs by content (ordering-agnostic).
// ---------------------------------------------------------------------------
__global__ void classify_kernel(const float* t0, const float* t1, const float* t2,
                                const int* p0, const int* p1, const int* p2, const int* p3,
                                const float* w0, const float* w1, const float* w2, const float* w3,
                                const float* wr) {
    __shared__ int mres[4];
    int tid = threadIdx.x;
    int w = tid >> 5, lane = tid & 31;
    const int* arr = (w == 0) ? p0 : (w == 1) ? p1 : (w == 2) ? p2 : p3;
    int m = 0;
    for (int i = lane; i < NTOK; i += 32) m = max(m, arr[i]);
#pragma unroll
    for (int off = 16; off > 0; off >>= 1)
        m = max(m, __shfl_xor_sync(0xffffffffu, m, off));
    if (lane == 0) mres[w] = m;
    __syncthreads();
    if (tid == 0) {
        bool T0 = (mres[0] <= NT - 1), T1 = (mres[1] <= NT - 1);
        bool T2 = (mres[2] <= NT - 1), T3 = (mres[3] <= NT - 1);
        if (!T0 && !T1 && T2 && T3) {
            dp_fk = p0; dp_fq = p1; dp_tk = p2; dp_tq = p3;
            dp_kt = t0; dp_qt = t1; dp_vt = t2;
            dp_Wk = w0; dp_Wo = w1; dp_Wq = w2; dp_Wv = w3;
        } else if (T0 && T1 && !T2 && !T3) {
            dp_tq = p0; dp_tk = p1; dp_fq = p2; dp_fk = p3;
            dp_qt = t0; dp_kt = t1; dp_vt = t2;
            dp_Wq = w0; dp_Wk = w1; dp_Wv = w2; dp_Wo = w3;
        } else {
            dp_tq = p0; dp_fq = p1; dp_tk = p2; dp_fk = p3;
            dp_qt = t0; dp_kt = t1; dp_vt = t2;
            dp_Wq = w0; dp_Wk = w1; dp_Wv = w2; dp_Wo = w3;
        }
        dp_Wrpe = wr;
    }
}

// ---------------------------------------------------------------------------
// 1) RPE bias table
// ---------------------------------------------------------------------------
__global__ void bias_table_kernel() {
    int gid = blockIdx.x * blockDim.x + threadIdx.x;
    if (gid >= NH * TBL) return;
    int pos = gid >> 3;
    int h   = gid & 7;
    int dt  = pos / NDF;
    int df  = pos % NDF;
    float pt = (float)(dt - (NT - 1)) / (float)(NT - 1);
    float pf = (float)(df - (NF - 1)) / (float)(NF - 1);
    const float* w = dp_Wrpe + h * 32;
    float acc = 0.f;
    float lg = logf(10000.0f);
#pragma unroll
    for (int j = 0; j < NFREQ; j++) {
        float fr = expf(-lg * (float)j / (float)NFREQ);
        float at = pt * fr;
        float af = pf * fr;
        acc += sinf(at) * w[j];
        acc += cosf(at) * w[NFREQ + j];
        acc += sinf(af) * w[2 * NFREQ + j];
        acc += cosf(af) * w[3 * NFREQ + j];
    }
    g_table[h * TBL + pos] = acc;
}

// ---------------------------------------------------------------------------
// 1b) Bias matrix: g_B[h][q][k] = table[h][...], done ONCE (shared by batches)
// ---------------------------------------------------------------------------
__global__ void bias_mat_kernel() {
    int q = blockIdx.x;
    int h = blockIdx.y;
    int base = (dp_tq[q] + NT - 1) * NDF + dp_fq[q] + NF - 1;
    const float* tb = g_table + h * TBL;
    float* dst = g_B + ((size_t)h * NTOK + q) * BROW;
    for (int k = threadIdx.x; k < NTOK; k += 256)
        dst[k] = tb[base - (dp_tk[k] * NDF + dp_fk[k])];
}

// ---------------------------------------------------------------------------
// 2) GEMM: 128x64 tiles, 8x4 micro, fp32 SIMT.
//    sel 9: fused QKV mode — blockIdx.z selects input 1/2/3.
//    sel 0: output projection, row-major write to outp.
// ---------------------------------------------------------------------------
__global__ void __launch_bounds__(256) gemm_big(float* __restrict__ outp, int sel) {
    if (sel == 9) sel = 1 + blockIdx.z;
    const float* X;
    const float* W;
    if      (sel == 1) { X = dp_qt; W = dp_Wq; }
    else if (sel == 2) { X = dp_kt; W = dp_Wk; }
    else if (sel == 3) { X = dp_vt; W = dp_Wv; }
    else               { X = g_AO;  W = dp_Wo; }

    __shared__ float As[16 * 132];
    __shared__ float Bs[16 * 68];
    int tid = threadIdx.x;
    int ca = tid & 15;
    int ra = tid >> 4;
    int m0 = blockIdx.y << 7;
    int n0 = blockIdx.x << 6;

    float acc[8][4];
#pragma unroll
    for (int i = 0; i < 8; i++)
#pragma unroll
        for (int j = 0; j < 4; j++) acc[i][j] = 0.f;

    for (int k0 = 0; k0 < DM; k0 += 16) {
        __syncthreads();
#pragma unroll
        for (int j = 0; j < 2; j++) {
            int f = tid + j * 256;
            int m = f >> 2, k4 = f & 3;
            float4 v = *(const float4*)(X + (size_t)(m0 + m) * DM + k0 + (k4 << 2));
            As[(k4 * 4 + 0) * 132 + m] = v.x;
            As[(k4 * 4 + 1) * 132 + m] = v.y;
            As[(k4 * 4 + 2) * 132 + m] = v.z;
            As[(k4 * 4 + 3) * 132 + m] = v.w;
        }
        {
            int n = tid >> 2, k4 = tid & 3;
            float4 v = *(const float4*)(W + (size_t)(n0 + n) * DM + k0 + (k4 << 2));
            Bs[(k4 * 4 + 0) * 68 + n] = v.x;
            Bs[(k4 * 4 + 1) * 68 + n] = v.y;
            Bs[(k4 * 4 + 2) * 68 + n] = v.z;
            Bs[(k4 * 4 + 3) * 68 + n] = v.w;
        }
        __syncthreads();
#pragma unroll
        for (int k = 0; k < 16; k++) {
            float4 a0 = *(const float4*)&As[k * 132 + (ra << 2)];
            float4 a1 = *(const float4*)&As[k * 132 + 64 + (ra << 2)];
            float4 b  = *(const float4*)&Bs[k * 68 + (ca << 2)];
            acc[0][0] += a0.x * b.x; acc[0][1] += a0.x * b.y; acc[0][2] += a0.x * b.z; acc[0][3] += a0.x * b.w;
            acc[1][0] += a0.y * b.x; acc[1][1] += a0.y * b.y; acc[1][2] += a0.y * b.z; acc[1][3] += a0.y * b.w;
            acc[2][0] += a0.z * b.x; acc[2][1] += a0.z * b.y; acc[2][2] += a0.z * b.z; acc[2][3] += a0.z * b.w;
            acc[3][0] += a0.w * b.x; acc[3][1] += a0.w * b.y; acc[3][2] += a0.w * b.z; acc[3][3] += a0.w * b.w;
            acc[4][0] += a1.x * b.x; acc[4][1] += a1.x * b.y; acc[4][2] += a1.x * b.z; acc[4][3] += a1.x * b.w;
            acc[5][0] += a1.y * b.x; acc[5][1] += a1.y * b.y; acc[5][2] += a1.y * b.z; acc[5][3] += a1.y * b.w;
            acc[6][0] += a1.z * b.x; acc[6][1] += a1.z * b.y; acc[6][2] += a1.z * b.z; acc[6][3] += a1.z * b.w;
            acc[7][0] += a1.w * b.x; acc[7][1] += a1.w * b.y; acc[7][2] += a1.w * b.z; acc[7][3] += a1.w * b.w;
        }
    }

    int ncol = n0 + (ca << 2);
    if (sel == 0) {
#pragma unroll
        for (int i = 0; i < 8; i++) {
            int m = m0 + ((i < 4) ? (ra * 4 + i) : (64 + ra * 4 + i - 4));
            float4 o = make_float4(acc[i][0], acc[i][1], acc[i][2], acc[i][3]);
            *(float4*)(outp + (size_t)m * DM + ncol) = o;
        }
    } else {
        float* dst = (sel == 1) ? g_Q : (sel == 2) ? g_K : g_V;
        int h = ncol >> 5;
        int d = ncol & 31;
#pragma unroll
        for (int i = 0; i < 8; i++) {
            int m = m0 + ((i < 4) ? (ra * 4 + i) : (64 + ra * 4 + i - 4));
            int b = m / NTOK;
            int nn = m - b * NTOK;
            float4 o = make_float4(acc[i][0], acc[i][1], acc[i][2], acc[i][3]);
            *(float4*)(dst + (size_t)((b * NH + h) * NTOK + nn) * DK + d) = o;
        }
    }
}

// ---------------------------------------------------------------------------
// 3) Flash attention: QK AND PV in fp16 m16n8k16, max-free softmax,
//    g_B coalesced bias, swizzled conflict-free half2 V^T, occ 3.
// ---------------------------------------------------------------------------
__global__ void __launch_bounds__(256, 3) attn_kernel() {
    __shared__ __align__(16) unsigned sPQ[64 * 36];  // Q staging (stride 20) then P half2 (stride 36)
    __shared__ __align__(16) unsigned sKh[64 * 20];  // K half2 pairs, stride 20
    __shared__ __align__(16) unsigned sVh[32 * 36];  // V^T half2 [d][kpair^swz], stride 36
    __shared__ float sRedS[2][64];

    int tid = threadIdx.x;
    int lane = tid & 31;
    int w = tid >> 5;
    int wm = w >> 1;           // 0..3 -> q rows wm*16..+15
    int wn = w & 1;            // 0..1 -> key/dim half
    int r4 = lane >> 2;        // 0..7
    int cl = lane & 3;         // 0..3
    int q0 = blockIdx.x << 6;
    int h = blockIdx.y, b = blockIdx.z;
    int bh = b * NH + h;

    const float4* Q4 = (const float4*)(g_Q + (size_t)bh * NTOK * DK);
    const float4* K4 = (const float4*)(g_K + (size_t)bh * NTOK * DK);
    const float4* V4 = (const float4*)(g_V + (size_t)bh * NTOK * DK);

    // --- stage Q (scaled) as packed half2, stride 20 words ---
    const float invs = 0.17677669529663688f;   // 1/sqrt(32)
#pragma unroll
    for (int j = 0; j < 2; j++) {
        int f = tid + j * 256;
        int r = f >> 3, c4 = f & 7;
        int qr = q0 + r;
        float4 v = make_float4(0.f, 0.f, 0.f, 0.f);
        if (qr < NTOK) v = Q4[qr * 8 + c4];
        uint2 qw;
        qw.x = packh2(v.x * invs, v.y * invs);
        qw.y = packh2(v.z * invs, v.w * invs);
        *(uint2*)&sPQ[r * 20 + 2 * c4] = qw;
    }
    __syncthreads();

    // --- extract Q fp16 fragments (held for all chunks): 2 ks x 4 regs ---
    int row0 = wm * 16 + r4;
    int row1 = row0 + 8;
    unsigned qf[2][4];
#pragma unroll
    for (int ks = 0; ks < 2; ks++) {
        int wd = ks * 8 + cl;
        qf[ks][0] = sPQ[row0 * 20 + wd];
        qf[ks][1] = sPQ[row1 * 20 + wd];
        qf[ks][2] = sPQ[row0 * 20 + wd + 4];
        qf[ks][3] = sPQ[row1 * 20 + wd + 4];
    }
    const float* Bq0 = g_B + ((size_t)h * NTOK + min(q0 + row0, NTOK - 1)) * BROW;
    const float* Bq1 = g_B + ((size_t)h * NTOK + min(q0 + row1, NTOK - 1)) * BROW;

    float l0r = 0.f, l1r = 0.f;
    float4 o0 = make_float4(0.f, 0.f, 0.f, 0.f);
    float4 o1 = make_float4(0.f, 0.f, 0.f, 0.f);

    int pr = tid >> 3;             // KV load row 0..31 (j=0) / +32 (j=1)
    int pc4 = tid & 7;             // KV load col group
    int vsw = pc4 << 1;            // V^T swizzle for this thread's d group

    for (int kc = 0; kc < 16; kc++) {
        int k0 = kc << 6;

        // --- bias loads (register-only; overlap the barrier drain) ---
        float2 b0v[4], b1v[4];
#pragma unroll
        for (int nt = 0; nt < 4; nt++) {
            int col = k0 + wn * 32 + nt * 8 + 2 * cl;   // < 1024 (padded row)
            b0v[nt] = *(const float2*)(Bq0 + col);
            b1v[nt] = *(const float2*)(Bq1 + col);
        }

        __syncthreads();   // prior chunk readers done before KV overwrite
        // --- load + convert + store this chunk's KV ---
#pragma unroll
        for (int j = 0; j < 2; j++) {
            int kr = k0 + pr + j * 32;
            float4 kv = make_float4(0.f, 0.f, 0.f, 0.f);
            float4 vv = make_float4(0.f, 0.f, 0.f, 0.f);
            if (kr < NTOK) {
                kv = K4[kr * 8 + pc4];
                vv = V4[kr * 8 + pc4];
            }
            int r = pr + j * 32;
            uint2 kw;
            kw.x = packh2(kv.x, kv.y);
            kw.y = packh2(kv.z, kv.w);
            *(uint2*)&sKh[r * 20 + 2 * pc4] = kw;
            // V^T half2: pair adjacent-k threads (tid^8 flips pr bit0)
            unsigned vw0 = packh2(vv.x, vv.y);
            unsigned vw1 = packh2(vv.z, vv.w);
            unsigned pw0 = __shfl_xor_sync(0xffffffffu, vw0, 8);
            unsigned pw1 = __shfl_xor_sync(0xffffffffu, vw1, 8);
            if (!(tid & 8)) {      // even-k thread stores the pairs
                int kp = (pr >> 1) + j * 16;
                int d0 = pc4 << 2;
                sVh[(d0 + 0) * 36 + (kp ^ vsw)] = __byte_perm(vw0, pw0, 0x5410);
                sVh[(d0 + 1) * 36 + (kp ^ vsw)] = __byte_perm(vw0, pw0, 0x7632);
                sVh[(d0 + 2) * 36 + (kp ^ vsw)] = __byte_perm(vw1, pw1, 0x5410);
                sVh[(d0 + 3) * 36 + (kp ^ vsw)] = __byte_perm(vw1, pw1, 0x7632);
            }
        }
        __syncthreads();

        // --- scores: S = Q K^T, fp16 m16n8k16 (per warp: 16q x 32k, 8 mmas) ---
        float4 c[4];
#pragma unroll
        for (int nt = 0; nt < 4; nt++) c[nt] = make_float4(0.f, 0.f, 0.f, 0.f);
#pragma unroll
        for (int nt = 0; nt < 4; nt++) {
            int kb = (wn * 32 + nt * 8 + r4) * 20;
#pragma unroll
            for (int ks = 0; ks < 2; ks++) {
                int wd = ks * 8 + cl;
                unsigned b0 = sKh[kb + wd];
                unsigned b1 = sKh[kb + wd + 4];
                mma_f16(c[nt], qf[ks][0], qf[ks][1], qf[ks][2], qf[ks][3], b0, b1);
            }
        }

        // --- bias + exp (max-free) + partial sums + write P (half2 pairs) ---
        int rem = NTOK - k0;
#pragma unroll
        for (int nt = 0; nt < 4; nt++) {
            int col0 = wn * 32 + nt * 8 + 2 * cl;
            bool v0 = col0 < rem, v1 = col0 + 1 < rem;
            c[nt].x = v0 ? __expf(c[nt].x + b0v[nt].x) : 0.f;
            c[nt].y = v1 ? __expf(c[nt].y + b0v[nt].y) : 0.f;
            c[nt].z = v0 ? __expf(c[nt].z + b1v[nt].x) : 0.f;
            c[nt].w = v1 ? __expf(c[nt].w + b1v[nt].y) : 0.f;
            l0r += c[nt].x + c[nt].y;
            l1r += c[nt].z + c[nt].w;
            int pw = wn * 16 + nt * 4 + cl;    // k-pair word index
            sPQ[row0 * 36 + pw] = packh2(c[nt].x, c[nt].y);
            sPQ[row1 * 36 + pw] = packh2(c[nt].z, c[nt].w);
        }
        __syncthreads();

        // --- PV: O += P V, fp16 m16n8k16 (per warp: 16q x 16d, 8 mmas) ---
#pragma unroll
        for (int ks = 0; ks < 4; ks++) {
            int wP = ks * 8 + cl;
            unsigned a0 = sPQ[row0 * 36 + wP];
            unsigned a1 = sPQ[row1 * 36 + wP];
            unsigned a2 = sPQ[row0 * 36 + wP + 4];
            unsigned a3 = sPQ[row1 * 36 + wP + 4];
#pragma unroll
            for (int dd = 0; dd < 2; dd++) {
                int dcol = wn * 16 + dd * 8 + r4;
                int sw = ((dcol >> 2) & 7) << 1;
                unsigned b0 = sVh[dcol * 36 + ((ks * 8 + cl) ^ sw)];
                unsigned b1 = sVh[dcol * 36 + ((ks * 8 + cl + 4) ^ sw)];
                if (dd == 0) mma_f16(o0, a0, a1, a2, a3, b0, b1);
                else         mma_f16(o1, a0, a1, a2, a3, b0, b1);
            }
        }
    }

    // --- epilogue: one-time row-sum reduction, then normalize & store ---
    l0r += __shfl_xor_sync(0xffffffffu, l0r, 1);
    l0r += __shfl_xor_sync(0xffffffffu, l0r, 2);
    l1r += __shfl_xor_sync(0xffffffffu, l1r, 1);
    l1r += __shfl_xor_sync(0xffffffffu, l1r, 2);
    if (cl == 0) {
        sRedS[wn][row0] = l0r;
        sRedS[wn][row1] = l1r;
    }
    __syncthreads();
    float inv0 = 1.0f / (sRedS[0][row0] + sRedS[1][row0]);
    float inv1 = 1.0f / (sRedS[0][row1] + sRedS[1][row1]);

    int qr0 = q0 + row0, qr1 = q0 + row1;
    int dbase = h * DK + wn * 16 + 2 * cl;
    if (qr0 < NTOK) {
        *(float2*)&g_AO[(size_t)(b * NTOK + qr0) * DM + dbase] =
            make_float2(o0.x * inv0, o0.y * inv0);
        *(float2*)&g_AO[(size_t)(b * NTOK + qr0) * DM + dbase + 8] =
            make_float2(o1.x * inv0, o1.y * inv0);
    }
    if (qr1 < NTOK) {
        *(float2*)&g_AO[(size_t)(b * NTOK + qr1) * DM + dbase] =
            make_float2(o0.z * inv1, o0.w * inv1);
        *(float2*)&g_AO[(size_t)(b * NTOK + qr1) * DM + dbase + 8] =
            make_float2(o1.z * inv1, o1.w * inv1);
    }
}

// ---------------------------------------------------------------------------
// Launch
// ---------------------------------------------------------------------------
extern "C" void kernel_launch(void* const* d_in, const int* in_sizes, int n_in,
                              void* d_out, int out_size) {
    const void* tok[3] = {0, 0, 0};
    const void* pos[4] = {0, 0, 0, 0};
    const void* wgt[4] = {0, 0, 0, 0};
    const void* wrpe = 0;
    int ntok = 0, npos = 0, nw = 0;
    for (int i = 0; i < n_in; i++) {
        int s = in_sizes[i];
        if (s == MTOT * DM && ntok < 3)      tok[ntok++] = d_in[i];
        else if (s == NTOK && npos < 4)      pos[npos++] = d_in[i];
        else if (s == DM * DM && nw < 4)     wgt[nw++]   = d_in[i];
        else if (s == NH * 32)               wrpe        = d_in[i];
    }
    if (ntok != 3 || npos != 4 || nw != 4 || !wrpe) {
        tok[0] = d_in[0]; tok[1] = d_in[1]; tok[2] = d_in[2];
        pos[0] = d_in[3]; pos[1] = d_in[4]; pos[2] = d_in[5]; pos[3] = d_in[6];
        int base = n_in - 5;
        wgt[0] = d_in[base]; wgt[1] = d_in[base + 1];
        wgt[2] = d_in[base + 2]; wgt[3] = d_in[base + 3];
        wrpe = d_in[base + 4];
    }
    float* out = (float*)d_out;

    classify_kernel<<<1, 128>>>(
        (const float*)tok[0], (const float*)tok[1], (const float*)tok[2],
        (const int*)pos[0], (const int*)pos[1], (const int*)pos[2], (const int*)pos[3],
        (const float*)wgt[0], (const float*)wgt[1], (const float*)wgt[2], (const float*)wgt[3],
        (const float*)wrpe);

    bias_table_kernel<<<(NH * TBL + 255) / 256, 256>>>();

    // Build the full (h, q, k) bias matrix once — shared across all batches
    bias_mat_kernel<<<dim3(NTOK, NH), 256>>>();

    // fused QKV projection: blockIdx.z selects input (grid 4 x 63 x 3)
    gemm_big<<<dim3(DM / 64, MTOT / 128, 3), 256>>>(nullptr, 9);

    dim3 agrid((NTOK + 63) / 64, NH, BB);     // (16, 8, 8)
    attn_kernel<<<agrid, 256>>>();

    gemm_big<<<dim3(DM / 64, MTOT / 128), 256>>>(out, 0);
}